// round 1
// baseline (speedup 1.0000x reference)
#include <cuda_runtime.h>
#include <cuda_bf16.h>
#include <cstdint>

// Problem constants (from reference)
#define IMG_W 1536
#define IMG_H 1536
#define STRIDE 2
#define W_OUT (IMG_W / STRIDE)   // 768
#define H_OUT (IMG_H / STRIDE)   // 768
#define N_BOX 64

// Scratch: per-column / per-row 64-bit box membership masks.
// col mask bit b set  <=>  xc(x) in [x1_b, x2_b]  AND  area_ok(b)
// row mask bit b set  <=>  yc(y) in [y1_b, y2_b]
__device__ unsigned long long g_colmask[W_OUT];
__device__ unsigned long long g_rowmask[H_OUT];

// ---------------------------------------------------------------------------
// Kernel 1: build masks + zero the 128-float output.
// 2048 threads total: [0,768) columns, [768,1536) rows, [1536,1664) zero out.
// ---------------------------------------------------------------------------
__global__ void build_masks_kernel(const float* __restrict__ bboxes,
                                   float* __restrict__ out) {
    int t = blockIdx.x * blockDim.x + threadIdx.x;

    if (t < W_OUT) {
        // column mask for x = t
        float xc = (float)t * (float)STRIDE + (float)STRIDE * 0.5f;
        unsigned long long m = 0ull;
        #pragma unroll 8
        for (int b = 0; b < N_BOX; b++) {
            float x1 = bboxes[b * 5 + 0];
            float y1 = bboxes[b * 5 + 1];
            float x2 = bboxes[b * 5 + 2];
            float y2 = bboxes[b * 5 + 3];
            bool area_ok = ((x2 - x1) * (y2 - y1)) != 0.0f;
            if (area_ok && xc >= x1 && xc <= x2)
                m |= (1ull << b);
        }
        g_colmask[t] = m;
    } else if (t < 2 * H_OUT) {
        // row mask for y = t - 768
        int r = t - W_OUT;
        float yc = (float)r * (float)STRIDE + (float)STRIDE * 0.5f;
        unsigned long long m = 0ull;
        #pragma unroll 8
        for (int b = 0; b < N_BOX; b++) {
            float y1 = bboxes[b * 5 + 1];
            float y2 = bboxes[b * 5 + 3];
            if (yc >= y1 && yc <= y2)
                m |= (1ull << b);
        }
        g_rowmask[r] = m;
    } else if (t < 2 * H_OUT + 2 * N_BOX) {
        // zero scores[64] + valid[64]
        out[t - 2 * H_OUT] = 0.0f;
    }
}

// ---------------------------------------------------------------------------
// Kernel 2: one block per row; 256 threads, 3 pixels each.
// Pixel mask m = row_mask[y] & col_mask[x]; contributes iff popc(m) == 1.
// Block-local max in shared, then one global atomicMax per nonzero box.
// sigmoid(x) > 0 strictly, so float-bit atomicMax with 0-init is exact and
// valid <=> a block ever produced a positive local max for that box.
// ---------------------------------------------------------------------------
__global__ void __launch_bounds__(256)
score_kernel(const float* __restrict__ conf, float* __restrict__ out) {
    __shared__ int smax[N_BOX];
    int tid = threadIdx.x;
    if (tid < N_BOX) smax[tid] = 0;
    __syncthreads();

    int y = blockIdx.x;
    unsigned long long rm = g_rowmask[y];
    if (rm != 0ull) {
        const float* row = conf + (size_t)y * W_OUT;
        #pragma unroll
        for (int i = 0; i < 3; i++) {
            int x = tid + i * 256;
            unsigned long long m = rm & g_colmask[x];
            // exactly one box covers this pixel?
            if (m != 0ull && (m & (m - 1ull)) == 0ull) {
                int b = __ffsll((long long)m) - 1;
                float c = row[x];
                float s = 1.0f / (1.0f + __expf(-c));
                atomicMax(&smax[b], __float_as_int(s));
            }
        }
    }
    __syncthreads();

    if (tid < N_BOX) {
        int v = smax[tid];
        if (v > 0) {
            atomicMax((int*)&out[tid], v);
            out[N_BOX + tid] = 1.0f;  // idempotent
        }
    }
}

// ---------------------------------------------------------------------------
extern "C" void kernel_launch(void* const* d_in, const int* in_sizes, int n_in,
                              void* d_out, int out_size) {
    const float* conf   = (const float*)d_in[0];  // (1,1,768,768) f32
    const float* bboxes = (const float*)d_in[2];  // (64,5) f32
    float* out = (float*)d_out;                   // scores[64] ++ valid[64]

    // Kernel 1: 2048 threads covers 768 cols + 768 rows + 128 output zeros.
    build_masks_kernel<<<8, 256>>>(bboxes, out);

    // Kernel 2: one block per row.
    score_kernel<<<H_OUT, 256>>>(conf, out);
}

// round 2
// speedup vs baseline: 1.0076x; 1.0076x over previous
#include <cuda_runtime.h>
#include <cuda_bf16.h>
#include <cstdint>

// Problem constants (from reference)
#define IMG_W 1536
#define IMG_H 1536
#define STRIDE 2
#define W_OUT (IMG_W / STRIDE)   // 768
#define H_OUT (IMG_H / STRIDE)   // 768
#define N_BOX 64

// Scratch: per-column / per-row 64-bit box membership masks.
// col mask bit b set  <=>  xc(x) in [x1_b, x2_b]  AND  area_ok(b)
// row mask bit b set  <=>  yc(y) in [y1_b, y2_b]
__device__ unsigned long long g_colmask[W_OUT];
__device__ unsigned long long g_rowmask[H_OUT];

// ---------------------------------------------------------------------------
// Kernel 1: build masks + zero the 128-float output.
// 2048 threads total: [0,768) columns, [768,1536) rows, tail zeroes out[128].
// ---------------------------------------------------------------------------
__global__ void build_masks_kernel(const float* __restrict__ bboxes,
                                   float* __restrict__ out) {
    int t = blockIdx.x * blockDim.x + threadIdx.x;

    if (t < W_OUT) {
        float xc = (float)t * (float)STRIDE + (float)STRIDE * 0.5f;
        unsigned long long m = 0ull;
        #pragma unroll 8
        for (int b = 0; b < N_BOX; b++) {
            float x1 = bboxes[b * 5 + 0];
            float y1 = bboxes[b * 5 + 1];
            float x2 = bboxes[b * 5 + 2];
            float y2 = bboxes[b * 5 + 3];
            bool area_ok = ((x2 - x1) * (y2 - y1)) != 0.0f;
            if (area_ok && xc >= x1 && xc <= x2)
                m |= (1ull << b);
        }
        g_colmask[t] = m;
    } else if (t < 2 * H_OUT) {
        int r = t - W_OUT;
        float yc = (float)r * (float)STRIDE + (float)STRIDE * 0.5f;
        unsigned long long m = 0ull;
        #pragma unroll 8
        for (int b = 0; b < N_BOX; b++) {
            float y1 = bboxes[b * 5 + 1];
            float y2 = bboxes[b * 5 + 3];
            if (yc >= y1 && yc <= y2)
                m |= (1ull << b);
        }
        g_rowmask[r] = m;
    } else if (t < 2 * H_OUT + 2 * N_BOX) {
        out[t - 2 * H_OUT] = 0.0f;
    }
}

// ---------------------------------------------------------------------------
// Kernel 2: one block per row; 192 threads, 4 pixels each (float4).
// Accumulate RAW conf max per box via an order-preserving unsigned key
// (sigmoid is monotone => max commutes), apply sigmoid once per (block,box).
// key(u) = u | 0x80000000 for non-negative floats, ~u for negatives;
// key of any finite float is > 0, so 0 is a safe "unset" sentinel.
// ---------------------------------------------------------------------------
__global__ void __launch_bounds__(192)
score_kernel(const float* __restrict__ conf, float* __restrict__ out) {
    int y = blockIdx.x;
    unsigned long long rm = g_rowmask[y];
    if (rm == 0ull) return;   // uniform per block

    __shared__ unsigned smax[N_BOX];
    int tid = threadIdx.x;
    if (tid < N_BOX) smax[tid] = 0u;
    __syncthreads();

    int x0 = tid * 4;
    // Front-batch all loads (independent -> MLP 3)
    const float4 c4 = *reinterpret_cast<const float4*>(
        conf + (size_t)y * W_OUT + x0);
    const ulonglong2 cmA = *reinterpret_cast<const ulonglong2*>(&g_colmask[x0]);
    const ulonglong2 cmB = *reinterpret_cast<const ulonglong2*>(&g_colmask[x0 + 2]);

    unsigned long long mm[4] = { rm & cmA.x, rm & cmA.y, rm & cmB.x, rm & cmB.y };
    float cv[4] = { c4.x, c4.y, c4.z, c4.w };

    #pragma unroll
    for (int i = 0; i < 4; i++) {
        unsigned long long m = mm[i];
        if (m != 0ull && (m & (m - 1ull)) == 0ull) {   // exactly one box
            int b = __ffsll((long long)m) - 1;
            unsigned u = __float_as_uint(cv[i]);
            unsigned key = (u & 0x80000000u) ? ~u : (u | 0x80000000u);
            atomicMax(&smax[b], key);
        }
    }
    __syncthreads();

    if (tid < N_BOX) {
        unsigned k = smax[tid];
        if (k != 0u) {
            unsigned u = (k & 0x80000000u) ? (k & 0x7FFFFFFFu) : ~k;
            float f = __uint_as_float(u);
            float s = 1.0f / (1.0f + __expf(-f));   // s > 0 strictly
            atomicMax((int*)&out[tid], __float_as_int(s)); // positive floats: int order ok
            out[N_BOX + tid] = 1.0f;  // idempotent
        }
    }
}

// ---------------------------------------------------------------------------
extern "C" void kernel_launch(void* const* d_in, const int* in_sizes, int n_in,
                              void* d_out, int out_size) {
    const float* conf   = (const float*)d_in[0];  // (1,1,768,768) f32
    const float* bboxes = (const float*)d_in[2];  // (64,5) f32
    float* out = (float*)d_out;                   // scores[64] ++ valid[64]

    build_masks_kernel<<<8, 256>>>(bboxes, out);
    score_kernel<<<H_OUT, 192>>>(conf, out);
}